// round 13
// baseline (speedup 1.0000x reference)
#include <cuda_runtime.h>
#include <cuda_bf16.h>
#include <cuda_fp16.h>
#include <cstdint>

// ---------------------------------------------------------------------------
// GCN 4-layer. GEMMs: mma.sync bf16 m16n8k16 HMMA, bf16x3 split
//   (x@W ~= hi@Whi + hi@Wlo + lo@Whi, fp32 accum).
// out_norm applied in the AGGREGATE (not GEMM epilogue) so layer-0 GEMM is
// independent of graph preprocessing -> preprocessing runs on a forked
// capture stream concurrently with weight_prep + GEMM0.
// Activations stored pre-split bf16 hi/lo; messages g_h fp16.
// edge_index INT32: ei[0..E)=src, ei[E..2E)=dst.
// ---------------------------------------------------------------------------

#define NN_MAX 50000
#define EE_MAX 800000
#define WT_TOTAL 73728   // 128*256 + 128*128 + 128*128 + 64*128

__device__ __align__(16) __half g_h [NN_MAX * 128];            // fp16 messages
__device__ __align__(16) __nv_bfloat16 g_act_hi[NN_MAX * 128]; // act hi
__device__ __align__(16) __nv_bfloat16 g_act_lo[NN_MAX * 128]; // act lo
__device__ float g_non[NN_MAX];
__device__ float g_nin[NN_MAX];
__device__ int   g_cout[NN_MAX];
__device__ int   g_cin [NN_MAX];
__device__ int   g_off [NN_MAX];
__device__ int   g_cur [NN_MAX];
__device__ int   g_csrc[EE_MAX];
__device__ int   g_total;
__device__ __align__(16) __nv_bfloat16 g_wt_hi[WT_TOTAL]; // Wt[N,K] bf16 hi
__device__ __align__(16) __nv_bfloat16 g_wt_lo[WT_TOTAL]; // Wt[N,K] bf16 lo

// --------------------------- helpers ----------------------------------------

__device__ __forceinline__ uint32_t smem_u32(const void* p) {
    uint32_t a;
    asm("{ .reg .u64 t; cvta.to.shared.u64 t, %1; cvt.u32.u64 %0, t; }"
        : "=r"(a) : "l"(p));
    return a;
}

__device__ __forceinline__ void ldmatrix_x4(uint32_t& r0, uint32_t& r1,
                                            uint32_t& r2, uint32_t& r3,
                                            uint32_t addr) {
    asm volatile("ldmatrix.sync.aligned.m8n8.x4.shared.b16 {%0,%1,%2,%3}, [%4];"
                 : "=r"(r0), "=r"(r1), "=r"(r2), "=r"(r3) : "r"(addr));
}

__device__ __forceinline__ void mma_bf16(float* d, const uint32_t* a, const uint32_t* b) {
    asm volatile(
        "mma.sync.aligned.m16n8k16.row.col.f32.bf16.bf16.f32 "
        "{%0,%1,%2,%3}, {%4,%5,%6,%7}, {%8,%9}, {%0,%1,%2,%3};"
        : "+f"(d[0]), "+f"(d[1]), "+f"(d[2]), "+f"(d[3])
        : "r"(a[0]), "r"(a[1]), "r"(a[2]), "r"(a[3]), "r"(b[0]), "r"(b[1]));
}

// --------------------------- preprocessing ----------------------------------

__global__ void zero_counts_kernel(int n) {
    int i = blockIdx.x * blockDim.x + threadIdx.x;
    if (i < n) { g_cout[i] = 0; g_cin[i] = 0; }
    if (i == 0) g_total = 0;
}

__global__ void count_deg_kernel(const int* __restrict__ ei, int E) {
    int i = blockIdx.x * blockDim.x + threadIdx.x;
    if (i >= 2 * E) return;
    int v = ei[i];
    if (i < E) atomicAdd(&g_cout[v], 1);
    else       atomicAdd(&g_cin[v], 1);
}

__global__ void norms_alloc_kernel(int n) {
    int i = blockIdx.x * blockDim.x + threadIdx.x;
    if (i >= n) return;
    int cin  = g_cin[i];
    int cout = g_cout[i];
    g_non[i] = rsqrtf(fmaxf((float)cout, 1.0f));
    g_nin[i] = rsqrtf(fmaxf((float)cin,  1.0f));
    int beg = atomicAdd(&g_total, cin);
    g_off[i] = beg;
    g_cur[i] = beg;
}

__global__ void fill_csr_kernel(const int* __restrict__ ei, int E) {
    int e = blockIdx.x * blockDim.x + threadIdx.x;
    if (e >= E) return;
    int s = ei[e];
    int d = ei[E + e];
    int pos = atomicAdd(&g_cur[d], 1);
    g_csrc[pos] = s;
}

// Wt_{hi,lo}[n*K + k] = split(W[k*N + n]); layers packed at fixed offsets.
__global__ void weight_prep_kernel(const float* __restrict__ W0, const float* __restrict__ W1,
                                   const float* __restrict__ W2, const float* __restrict__ W3) {
    int t = blockIdx.x * blockDim.x + threadIdx.x;
    if (t >= WT_TOTAL) return;
    const float* W; int K, N, i;
    if (t < 32768)      { W = W0; K = 256; N = 128; i = t; }
    else if (t < 49152) { W = W1; K = 128; N = 128; i = t - 32768; }
    else if (t < 65536) { W = W2; K = 128; N = 128; i = t - 49152; }
    else                { W = W3; K = 128; N = 64;  i = t - 65536; }
    int k = i % K, n = i / K;
    float v = W[k * N + n];
    __nv_bfloat16 hb = __float2bfloat16(v);
    float r = v - __bfloat162float(hb);
    g_wt_hi[t] = hb;
    g_wt_lo[t] = __float2bfloat16(r);
}

// --------------------------- tensor-core GEMM (bf16x3) ----------------------
// g_h[m][n] = fp16( sum_k A[m][k] * W[k][n] )   (no norm scale here)

template<int K, int N, bool A_FROM_ACT>
__global__ void __launch_bounds__(256) gemm_mma_kernel(
    const float* __restrict__ Ap, int wt_off, int M)
{
    constexpr int KT  = 64;
    constexpr int NCH = K / KT;
    constexpr int P   = 72;                 // smem pitch in bf16 elems
    constexpr int WM  = (N == 128) ? 64 : 32;
    constexpr int WN  = 32;
    constexpr int WGN = N / WN;
    constexpr int MT  = WM / 16;
    constexpr int NT  = WN / 8;

    extern __shared__ __nv_bfloat16 sm[];
    __nv_bfloat16* sAh = sm;                   // [128][P]
    __nv_bfloat16* sAl = sAh + 128 * P;
    __nv_bfloat16* sBh = sAl + 128 * P;        // [N][P]
    __nv_bfloat16* sBl = sBh + N * P;

    const int tid  = threadIdx.x;
    const int w    = tid >> 5;
    const int lane = tid & 31;
    const int gid  = lane >> 2;
    const int tig  = lane & 3;
    const int wm   = w / WGN, wn = w % WGN;
    const int m0   = blockIdx.x * 128;

    const __nv_bfloat16* __restrict__ wh = g_wt_hi + wt_off;
    const __nv_bfloat16* __restrict__ wl = g_wt_lo + wt_off;

    float acc[MT][NT][4];
#pragma unroll
    for (int mt = 0; mt < MT; mt++)
#pragma unroll
        for (int nt = 0; nt < NT; nt++)
#pragma unroll
            for (int j = 0; j < 4; j++) acc[mt][nt][j] = 0.0f;

    for (int ch = 0; ch < NCH; ch++) {
        const int k0g = ch * KT;
        // ---- A chunk: 128 rows x 64
#pragma unroll
        for (int it = 0; it < 4; it++) {
            int t = tid + it * 256;          // 128*8 items
            int row = t >> 3, g8 = t & 7;
            int gm = m0 + row;
            if (A_FROM_ACT) {
                uint4 hv = make_uint4(0,0,0,0), lv = make_uint4(0,0,0,0);
                if (gm < M) {
                    size_t gofs = (size_t)gm * K + k0g + g8 * 8;
                    hv = *reinterpret_cast<const uint4*>(g_act_hi + gofs);
                    lv = *reinterpret_cast<const uint4*>(g_act_lo + gofs);
                }
                *reinterpret_cast<uint4*>(sAh + row * P + g8 * 8) = hv;
                *reinterpret_cast<uint4*>(sAl + row * P + g8 * 8) = lv;
            } else {
                float f[8];
                if (gm < M) {
                    const float4* ap = reinterpret_cast<const float4*>(
                        Ap + (size_t)gm * K + k0g + g8 * 8);
                    float4 f0 = ap[0], f1 = ap[1];
                    f[0]=f0.x; f[1]=f0.y; f[2]=f0.z; f[3]=f0.w;
                    f[4]=f1.x; f[5]=f1.y; f[6]=f1.z; f[7]=f1.w;
                } else {
#pragma unroll
                    for (int j = 0; j < 8; j++) f[j] = 0.0f;
                }
                uint32_t hw[4], lw[4];
#pragma unroll
                for (int j = 0; j < 4; j++) {
                    __nv_bfloat16 h0 = __float2bfloat16(f[2*j]);
                    __nv_bfloat16 h1 = __float2bfloat16(f[2*j+1]);
                    float r0 = f[2*j]   - __bfloat162float(h0);
                    float r1 = f[2*j+1] - __bfloat162float(h1);
                    hw[j] = (uint32_t)__bfloat16_as_ushort(h0) |
                            ((uint32_t)__bfloat16_as_ushort(h1) << 16);
                    lw[j] = (uint32_t)__bfloat16_as_ushort(__float2bfloat16(r0)) |
                            ((uint32_t)__bfloat16_as_ushort(__float2bfloat16(r1)) << 16);
                }
                *reinterpret_cast<uint4*>(sAh + row * P + g8 * 8) =
                    make_uint4(hw[0], hw[1], hw[2], hw[3]);
                *reinterpret_cast<uint4*>(sAl + row * P + g8 * 8) =
                    make_uint4(lw[0], lw[1], lw[2], lw[3]);
            }
        }
        // ---- B chunk: N x 64 bf16 hi/lo
        for (int t = tid; t < N * 8; t += 256) {
            int n = t >> 3, g8 = t & 7;
            size_t gofs = (size_t)n * K + k0g + g8 * 8;
            *reinterpret_cast<uint4*>(sBh + n * P + g8 * 8) =
                *reinterpret_cast<const uint4*>(wh + gofs);
            *reinterpret_cast<uint4*>(sBl + n * P + g8 * 8) =
                *reinterpret_cast<const uint4*>(wl + gofs);
        }
        __syncthreads();

#pragma unroll
        for (int ks = 0; ks < 4; ks++) {
            const int k0 = ks * 16;
            uint32_t ah[MT][4], al[MT][4];
#pragma unroll
            for (int mt = 0; mt < MT; mt++) {
                int row = wm * WM + mt * 16 + (lane & 15);
                int kk  = k0 + (lane >> 4) * 8;
                ldmatrix_x4(ah[mt][0], ah[mt][1], ah[mt][2], ah[mt][3],
                            smem_u32(sAh + row * P + kk));
                ldmatrix_x4(al[mt][0], al[mt][1], al[mt][2], al[mt][3],
                            smem_u32(sAl + row * P + kk));
            }
            uint32_t bh[NT][2], bl[NT][2];
#pragma unroll
            for (int nt = 0; nt < NT; nt++) {
                int n = wn * WN + nt * 8 + gid;
                const __nv_bfloat16* ph = sBh + n * P + k0 + tig * 2;
                const __nv_bfloat16* pl = sBl + n * P + k0 + tig * 2;
                bh[nt][0] = *reinterpret_cast<const uint32_t*>(ph);
                bh[nt][1] = *reinterpret_cast<const uint32_t*>(ph + 8);
                bl[nt][0] = *reinterpret_cast<const uint32_t*>(pl);
                bl[nt][1] = *reinterpret_cast<const uint32_t*>(pl + 8);
            }
#pragma unroll
            for (int mt = 0; mt < MT; mt++)
#pragma unroll
                for (int nt = 0; nt < NT; nt++) {
                    mma_bf16(acc[mt][nt], ah[mt], bh[nt]);
                    mma_bf16(acc[mt][nt], ah[mt], bl[nt]);
                    mma_bf16(acc[mt][nt], al[mt], bh[nt]);
                }
        }
        __syncthreads();
    }

    // ---- epilogue: store fp16 messages (unscaled)
#pragma unroll
    for (int mt = 0; mt < MT; mt++) {
        int r0 = m0 + wm * WM + mt * 16 + gid;
        int r1 = r0 + 8;
#pragma unroll
        for (int nt = 0; nt < NT; nt++) {
            int n = wn * WN + nt * 8 + tig * 2;
            if (r0 < M) {
                __half2 o = __floats2half2_rn(acc[mt][nt][0], acc[mt][nt][1]);
                *reinterpret_cast<__half2*>(g_h + (size_t)r0 * N + n) = o;
            }
            if (r1 < M) {
                __half2 o = __floats2half2_rn(acc[mt][nt][2], acc[mt][nt][3]);
                *reinterpret_cast<__half2*>(g_h + (size_t)r1 * N + n) = o;
            }
        }
    }
}

// --------------------------- gather-aggregate --------------------------------
// acc += non[src] * h[src]; out = nin[d]*acc + b (+relu). MLP=4 unroll.

template<int N, bool RELU, bool TO_PARAM>
__global__ void aggregate_kernel(const float* __restrict__ bias,
                                 float* __restrict__ outp, int M) {
    constexpr int VPL = N / 32;
    int warp = (blockIdx.x * blockDim.x + threadIdx.x) >> 5;
    if (warp >= M) return;
    int lane = threadIdx.x & 31;

    int beg = g_off[warp];
    int end = beg + g_cin[warp];

    float acc[VPL];
#pragma unroll
    for (int c = 0; c < VPL; c++) acc[c] = 0.0f;

    int e = beg;
    for (; e + 3 < end; e += 4) {
        int s0 = g_csrc[e];
        int s1 = g_csrc[e + 1];
        int s2 = g_csrc[e + 2];
        int s3 = g_csrc[e + 3];
        float n0 = g_non[s0], n1 = g_non[s1], n2 = g_non[s2], n3 = g_non[s3];
        if (VPL == 4) {
            uint2 u0 = *reinterpret_cast<const uint2*>(g_h + (size_t)s0 * N + lane * 4);
            uint2 u1 = *reinterpret_cast<const uint2*>(g_h + (size_t)s1 * N + lane * 4);
            uint2 u2 = *reinterpret_cast<const uint2*>(g_h + (size_t)s2 * N + lane * 4);
            uint2 u3 = *reinterpret_cast<const uint2*>(g_h + (size_t)s3 * N + lane * 4);
            float2 a, b;
            a = __half22float2(*reinterpret_cast<__half2*>(&u0.x));
            b = __half22float2(*reinterpret_cast<__half2*>(&u0.y));
            acc[0] = fmaf(a.x, n0, acc[0]); acc[1] = fmaf(a.y, n0, acc[1]);
            acc[2] = fmaf(b.x, n0, acc[2]); acc[3] = fmaf(b.y, n0, acc[3]);
            a = __half22float2(*reinterpret_cast<__half2*>(&u1.x));
            b = __half22float2(*reinterpret_cast<__half2*>(&u1.y));
            acc[0] = fmaf(a.x, n1, acc[0]); acc[1] = fmaf(a.y, n1, acc[1]);
            acc[2] = fmaf(b.x, n1, acc[2]); acc[3] = fmaf(b.y, n1, acc[3]);
            a = __half22float2(*reinterpret_cast<__half2*>(&u2.x));
            b = __half22float2(*reinterpret_cast<__half2*>(&u2.y));
            acc[0] = fmaf(a.x, n2, acc[0]); acc[1] = fmaf(a.y, n2, acc[1]);
            acc[2] = fmaf(b.x, n2, acc[2]); acc[3] = fmaf(b.y, n2, acc[3]);
            a = __half22float2(*reinterpret_cast<__half2*>(&u3.x));
            b = __half22float2(*reinterpret_cast<__half2*>(&u3.y));
            acc[0] = fmaf(a.x, n3, acc[0]); acc[1] = fmaf(a.y, n3, acc[1]);
            acc[2] = fmaf(b.x, n3, acc[2]); acc[3] = fmaf(b.y, n3, acc[3]);
        } else {
            uint32_t u0 = *reinterpret_cast<const uint32_t*>(g_h + (size_t)s0 * N + lane * 2);
            uint32_t u1 = *reinterpret_cast<const uint32_t*>(g_h + (size_t)s1 * N + lane * 2);
            uint32_t u2 = *reinterpret_cast<const uint32_t*>(g_h + (size_t)s2 * N + lane * 2);
            uint32_t u3 = *reinterpret_cast<const uint32_t*>(g_h + (size_t)s3 * N + lane * 2);
            float2 a;
            a = __half22float2(*reinterpret_cast<__half2*>(&u0));
            acc[0] = fmaf(a.x, n0, acc[0]); acc[1] = fmaf(a.y, n0, acc[1]);
            a = __half22float2(*reinterpret_cast<__half2*>(&u1));
            acc[0] = fmaf(a.x, n1, acc[0]); acc[1] = fmaf(a.y, n1, acc[1]);
            a = __half22float2(*reinterpret_cast<__half2*>(&u2));
            acc[0] = fmaf(a.x, n2, acc[0]); acc[1] = fmaf(a.y, n2, acc[1]);
            a = __half22float2(*reinterpret_cast<__half2*>(&u3));
            acc[0] = fmaf(a.x, n3, acc[0]); acc[1] = fmaf(a.y, n3, acc[1]);
        }
    }
    for (; e < end; e++) {
        int s0 = g_csrc[e];
        float n0 = g_non[s0];
        if (VPL == 4) {
            uint2 u0 = *reinterpret_cast<const uint2*>(g_h + (size_t)s0 * N + lane * 4);
            float2 a = __half22float2(*reinterpret_cast<__half2*>(&u0.x));
            float2 b = __half22float2(*reinterpret_cast<__half2*>(&u0.y));
            acc[0] = fmaf(a.x, n0, acc[0]); acc[1] = fmaf(a.y, n0, acc[1]);
            acc[2] = fmaf(b.x, n0, acc[2]); acc[3] = fmaf(b.y, n0, acc[3]);
        } else {
            uint32_t u0 = *reinterpret_cast<const uint32_t*>(g_h + (size_t)s0 * N + lane * 2);
            float2 a = __half22float2(*reinterpret_cast<__half2*>(&u0));
            acc[0] = fmaf(a.x, n0, acc[0]); acc[1] = fmaf(a.y, n0, acc[1]);
        }
    }

    float s = g_nin[warp];
    if (TO_PARAM) {
        if (VPL == 4) {
            float4 b = reinterpret_cast<const float4*>(bias)[lane];
            float4 o;
            o.x = acc[0] * s + b.x; o.y = acc[1] * s + b.y;
            o.z = acc[2] * s + b.z; o.w = acc[3] * s + b.w;
            if (RELU) {
                o.x = fmaxf(o.x, 0.f); o.y = fmaxf(o.y, 0.f);
                o.z = fmaxf(o.z, 0.f); o.w = fmaxf(o.w, 0.f);
            }
            *reinterpret_cast<float4*>(outp + (size_t)warp * N + lane * 4) = o;
        } else {
            float2 b = reinterpret_cast<const float2*>(bias)[lane];
            float2 o;
            o.x = acc[0] * s + b.x; o.y = acc[1] * s + b.y;
            if (RELU) { o.x = fmaxf(o.x, 0.f); o.y = fmaxf(o.y, 0.f); }
            *reinterpret_cast<float2*>(outp + (size_t)warp * N + lane * 2) = o;
        }
    } else {
        float4 b = reinterpret_cast<const float4*>(bias)[lane];
        float o[4];
        o[0] = acc[0] * s + b.x; o[1] = acc[1] * s + b.y;
        o[2] = acc[2] * s + b.z; o[3] = acc[3] * s + b.w;
        if (RELU) {
#pragma unroll
            for (int j = 0; j < 4; j++) o[j] = fmaxf(o[j], 0.f);
        }
        uint32_t hw[2], lw[2];
#pragma unroll
        for (int j = 0; j < 2; j++) {
            __nv_bfloat16 h0 = __float2bfloat16(o[2*j]);
            __nv_bfloat16 h1 = __float2bfloat16(o[2*j+1]);
            float r0 = o[2*j]   - __bfloat162float(h0);
            float r1 = o[2*j+1] - __bfloat162float(h1);
            hw[j] = (uint32_t)__bfloat16_as_ushort(h0) |
                    ((uint32_t)__bfloat16_as_ushort(h1) << 16);
            lw[j] = (uint32_t)__bfloat16_as_ushort(__float2bfloat16(r0)) |
                    ((uint32_t)__bfloat16_as_ushort(__float2bfloat16(r1)) << 16);
        }
        size_t ofs = (size_t)warp * N + lane * 4;
        *reinterpret_cast<uint2*>(g_act_hi + ofs) = make_uint2(hw[0], hw[1]);
        *reinterpret_cast<uint2*>(g_act_lo + ofs) = make_uint2(lw[0], lw[1]);
    }
}

// --------------------------- launch ------------------------------------------

extern "C" void kernel_launch(void* const* d_in, const int* in_sizes, int n_in,
                              void* d_out, int out_size) {
    const float* x  = (const float*)d_in[0];
    const int*   ei = (const int*)d_in[1];
    const float* W0 = (const float*)d_in[2];
    const float* b0 = (const float*)d_in[3];
    const float* W1 = (const float*)d_in[4];
    const float* b1 = (const float*)d_in[5];
    const float* W2 = (const float*)d_in[6];
    const float* b2 = (const float*)d_in[7];
    const float* W3 = (const float*)d_in[8];
    const float* b3 = (const float*)d_in[9];
    float* out = (float*)d_out;

    const int M = in_sizes[0] / 256;   // 50000
    const int E = in_sizes[1] / 2;     // 800000
    const int T = 256;

    const int dyn128 = (128 + 128) * 72 * 2 * 2;   // 73728
    const int dyn64  = (128 + 64)  * 72 * 2 * 2;   // 55296
    cudaFuncSetAttribute(gemm_mma_kernel<256, 128, false>,
                         cudaFuncAttributeMaxDynamicSharedMemorySize, dyn128);
    cudaFuncSetAttribute(gemm_mma_kernel<128, 128, true>,
                         cudaFuncAttributeMaxDynamicSharedMemorySize, dyn128);
    cudaFuncSetAttribute(gemm_mma_kernel<128, 64, true>,
                         cudaFuncAttributeMaxDynamicSharedMemorySize, dyn64);

    // ---- fork: preprocessing runs concurrently with weight_prep + GEMM0.
    // (streams/events created per call and leaked: harness calls this ~2x;
    //  no device memory involved, graph sees only kernels + dependency edges)
    cudaStream_t sPre;
    cudaStreamCreateWithFlags(&sPre, cudaStreamNonBlocking);
    cudaEvent_t evFork, evPre;
    cudaEventCreateWithFlags(&evFork, cudaEventDisableTiming);
    cudaEventCreateWithFlags(&evPre,  cudaEventDisableTiming);

    cudaEventRecord(evFork, 0);
    cudaStreamWaitEvent(sPre, evFork, 0);

    // side stream: graph preprocessing chain
    zero_counts_kernel<<<(M + T - 1) / T, T, 0, sPre>>>(M);
    count_deg_kernel<<<(2 * E + T - 1) / T, T, 0, sPre>>>(ei, E);
    norms_alloc_kernel<<<(M + T - 1) / T, T, 0, sPre>>>(M);
    fill_csr_kernel<<<(E + T - 1) / T, T, 0, sPre>>>(ei, E);
    cudaEventRecord(evPre, sPre);

    const int gemm_blocks = (M + 127) / 128;   // 391
    const int agg_blocks  = (M * 32 + T - 1) / T;

    // main stream: weights + layer-0 GEMM (independent of preprocessing)
    weight_prep_kernel<<<(WT_TOTAL + T - 1) / T, T>>>(W0, W1, W2, W3);
    gemm_mma_kernel<256, 128, false><<<gemm_blocks, 256, dyn128>>>(x, 0, M);

    // join: aggregation needs CSR + norms
    cudaStreamWaitEvent(0, evPre, 0);

    aggregate_kernel<128, true, false><<<agg_blocks, T>>>(b0, nullptr, M);

    gemm_mma_kernel<128, 128, true><<<gemm_blocks, 256, dyn128>>>(nullptr, 32768, M);
    aggregate_kernel<128, true, false><<<agg_blocks, T>>>(b1, nullptr, M);

    gemm_mma_kernel<128, 128, true><<<gemm_blocks, 256, dyn128>>>(nullptr, 49152, M);
    aggregate_kernel<128, true, false><<<agg_blocks, T>>>(b2, nullptr, M);

    gemm_mma_kernel<128, 64, true><<<gemm_blocks, 256, dyn64>>>(nullptr, 65536, M);
    aggregate_kernel<64, false, true><<<agg_blocks, T>>>(b3, out, M);
}